// round 1
// baseline (speedup 1.0000x reference)
#include <cuda_runtime.h>
#include <math.h>

#define BROWS 2048
#define NCLS  1000
#define KDIM  2048
#define NSTEPS 100

#define LRc   0.1f
#define B1c   0.9f
#define B2c   0.999f
#define EPSc  1e-8f
#define BETAc 5.0f
#define TAUc  6.0f
#define PI_F  3.14159274101257324f   // float(np.pi)

// ---------------- device scratch (static, no allocation) ----------------
__device__ float g_z[BROWS * NCLS];
__device__ float g_m[BROWS * NCLS];
__device__ float g_v[BROWS * NCLS];
__device__ float g_T[BROWS * BROWS];      // l_trg, class-slot layout
__device__ float g_topz[BROWS];
__device__ float g_topu[BROWS];
__device__ float g_rowmax[BROWS];
__device__ float g_sumexp[BROWS];
__device__ int   g_rowarg[BROWS];
__device__ float g_ptrg[BROWS];
__device__ int   g_y[BROWS];
__device__ int   g_allowed[NCLS];
__device__ int   g_count[NCLS];
__device__ int   g_start[NCLS];
__device__ int   g_cursor[NCLS];
__device__ int   g_member[BROWS];         // row j, sorted by class
__device__ int   g_classOf[BROWS];        // class of slot k
__device__ float g_coef;
__device__ int   g_istar;
__device__ int   g_cstar;
__device__ float g_rmaxstar;
__device__ float g_sumexpstar;

// ---------------- GEMM: z = x @ W + b (fp32, 64x64x16 tiles) ----------------
__global__ void gemm_kernel(const float* __restrict__ x,
                            const float* __restrict__ W,
                            const float* __restrict__ bias) {
    __shared__ float As[64][16];
    __shared__ float Bs[16][64];
    int tid = threadIdx.x;
    int tx = tid & 15;            // N direction
    int ty = tid >> 4;            // M direction
    int row0 = blockIdx.y * 64;
    int col0 = blockIdx.x * 64;

    int lm = tid >> 2;            // 0..63
    int lk = (tid & 3) * 4;       // 0,4,8,12
    int bk = tid >> 4;            // 0..15
    int bn = (tid & 15) * 4;      // 0..60

    float acc[4][4];
#pragma unroll
    for (int i = 0; i < 4; ++i)
#pragma unroll
        for (int j = 0; j < 4; ++j) acc[i][j] = 0.f;

    for (int k0 = 0; k0 < KDIM; k0 += 16) {
        float4 xa = *reinterpret_cast<const float4*>(&x[(size_t)(row0 + lm) * KDIM + k0 + lk]);
        *reinterpret_cast<float4*>(&As[lm][lk]) = xa;
#pragma unroll
        for (int j = 0; j < 4; ++j) {
            int n = col0 + bn + j;
            Bs[bk][bn + j] = (n < NCLS) ? W[(size_t)(k0 + bk) * NCLS + n] : 0.f;
        }
        __syncthreads();
#pragma unroll
        for (int k = 0; k < 16; ++k) {
            float a0 = As[ty * 4 + 0][k];
            float a1 = As[ty * 4 + 1][k];
            float a2 = As[ty * 4 + 2][k];
            float a3 = As[ty * 4 + 3][k];
            float4 bb = *reinterpret_cast<const float4*>(&Bs[k][tx * 4]);
            acc[0][0] += a0 * bb.x; acc[0][1] += a0 * bb.y; acc[0][2] += a0 * bb.z; acc[0][3] += a0 * bb.w;
            acc[1][0] += a1 * bb.x; acc[1][1] += a1 * bb.y; acc[1][2] += a1 * bb.z; acc[1][3] += a1 * bb.w;
            acc[2][0] += a2 * bb.x; acc[2][1] += a2 * bb.y; acc[2][2] += a2 * bb.z; acc[2][3] += a2 * bb.w;
            acc[3][0] += a3 * bb.x; acc[3][1] += a3 * bb.y; acc[3][2] += a3 * bb.z; acc[3][3] += a3 * bb.w;
        }
        __syncthreads();
    }
#pragma unroll
    for (int i = 0; i < 4; ++i) {
        int row = row0 + ty * 4 + i;
#pragma unroll
        for (int j = 0; j < 4; ++j) {
            int col = col0 + tx * 4 + j;
            if (col < NCLS) g_z[(size_t)row * NCLS + col] = acc[i][j] + bias[col];
        }
    }
}

// ---------------- setup kernels ----------------
__global__ void init_class_kernel() {
    int c = blockIdx.x * blockDim.x + threadIdx.x;
    if (c < NCLS) { g_allowed[c] = 1; g_count[c] = 0; g_cursor[c] = 0; }
}

// per-row stats: rowmax, argmax (lowest-index tie), sumexp(exp(a - rowmax)),
// optionally masked top (allowed columns, floored at -1000).
// A == nullptr -> use g_z; isZ additionally stores y and p_trg.
__global__ void stats_kernel(const float* __restrict__ A, int withTop, int isZ) {
    int row = blockIdx.x;
    const float* a = (A ? A : (const float*)g_z) + (size_t)row * NCLS;
    int tid = threadIdx.x;

    float va[4];
    int   nv = 0;
    float vmax = -3.402823466e38f;
    int   vidx = NCLS;
    float tmax = -1000.0f;
    for (int c = tid; c < NCLS; c += 256) {
        float v = a[c];
        va[nv++] = v;
        if (v > vmax) { vmax = v; vidx = c; }
        if (withTop) { if (g_allowed[c] && v > tmax) tmax = v; }
    }

    __shared__ float smax[256];
    __shared__ int   sidx[256];
    __shared__ float stop_[256];
    __shared__ float ssum[256];
    smax[tid] = vmax; sidx[tid] = vidx; stop_[tid] = tmax;
    __syncthreads();
    for (int s = 128; s > 0; s >>= 1) {
        if (tid < s) {
            float ov = smax[tid + s]; int oi = sidx[tid + s];
            if (ov > smax[tid] || (ov == smax[tid] && oi < sidx[tid])) { smax[tid] = ov; sidx[tid] = oi; }
            float ot = stop_[tid + s];
            if (ot > stop_[tid]) stop_[tid] = ot;
        }
        __syncthreads();
    }
    float rmax = smax[0];

    float se = 0.f;
    for (int q = 0; q < nv; ++q) se += expf(va[q] - rmax);
    ssum[tid] = se;
    __syncthreads();
    for (int s = 128; s > 0; s >>= 1) {
        if (tid < s) ssum[tid] += ssum[tid + s];
        __syncthreads();
    }
    if (tid == 0) {
        g_rowmax[row] = rmax;
        g_sumexp[row] = ssum[0];
        g_rowarg[row] = sidx[0];
        if (withTop) g_topu[row] = stop_[0];
        if (isZ) { g_y[row] = sidx[0]; g_ptrg[row] = 1.0f / ssum[0]; }
    }
}

__global__ void mark_kernel() {   // build allowed mask + class counts
    int i = blockIdx.x * blockDim.x + threadIdx.x;
    if (i < BROWS) {
        int c = g_y[i];
        g_allowed[c] = 0;
        atomicAdd(&g_count[c], 1);
    }
}

__global__ void scan_kernel() {   // exclusive prefix sum over 1000 classes
    if (threadIdx.x == 0 && blockIdx.x == 0) {
        int s = 0;
        for (int c = 0; c < NCLS; ++c) { g_start[c] = s; s += g_count[c]; }
    }
}

__global__ void scatter_kernel() {
    int i = blockIdx.x * blockDim.x + threadIdx.x;
    if (i < BROWS) {
        int c = g_y[i];
        int pos = g_start[c] + atomicAdd(&g_cursor[c], 1);
        g_member[pos]  = i;
        g_classOf[pos] = c;
    }
}

__global__ void topz_kernel() {   // top_z[row] = max over allowed cols (floor -1000)
    int row = blockIdx.x;
    int tid = threadIdx.x;
    float tmax = -1000.0f;
    for (int c = tid; c < NCLS; c += 256) {
        if (g_allowed[c]) {
            float v = g_z[(size_t)row * NCLS + c];
            if (v > tmax) tmax = v;
        }
    }
    __shared__ float st[256];
    st[tid] = tmax;
    __syncthreads();
    for (int s = 128; s > 0; s >>= 1) {
        if (tid < s) { float o = st[tid + s]; if (o > st[tid]) st[tid] = o; }
        __syncthreads();
    }
    if (tid == 0) g_topz[row] = st[0];
}

// T[i][k] = l_trg for row i, class-slot k  (iteration-invariant)
__global__ void computeT_kernel() {
    int idx = blockIdx.x * blockDim.x + threadIdx.x;   // 2048*2048 threads
    int i = idx >> 11;
    int k = idx & 2047;
    int c = g_classOf[k];
    int j = g_member[k];
    float lorg = g_z[(size_t)i * NCLS + c] - g_topz[j];
    float latr = (floorf(lorg / TAUc) + 0.5f) * TAUc;
    float arg  = PI_F * (1.0f - 2.0f * (lorg - latr) / TAUc);
    g_T[idx] = lorg - TAUc * sinf(arg);   // ALPHA = 1
}

__global__ void init_u_kernel(float* __restrict__ u) {
    int idx = blockIdx.x * blockDim.x + threadIdx.x;
    u[idx]   = g_z[idx];
    g_m[idx] = 0.f;
    g_v[idx] = 0.f;
}

// ---------------- per-step kernels ----------------
// single block: i* = argmax_i (1/sumexp)  (== argmin sumexp, lowest-index tie),
// pmax, S = sum_j sign(pmax - p_trg_j), coefficient for the softmax-grad term.
__global__ void reduce_kernel() {
    __shared__ float sv[1024];
    __shared__ int   si[1024];
    __shared__ float ss[1024];
    int tid = threadIdx.x;
    float best = g_sumexp[tid];
    int   bi   = tid;
    float o = g_sumexp[tid + 1024];
    if (o < best) { best = o; bi = tid + 1024; }
    sv[tid] = best; si[tid] = bi;
    __syncthreads();
    for (int s = 512; s > 0; s >>= 1) {
        if (tid < s) {
            float ov = sv[tid + s]; int oi = si[tid + s];
            if (ov < sv[tid] || (ov == sv[tid] && oi < si[tid])) { sv[tid] = ov; si[tid] = oi; }
        }
        __syncthreads();
    }
    int istar = si[0];
    float pmax = 1.0f / sv[0];

    float s1 = 0.f;
    for (int j = tid; j < BROWS; j += 1024) {
        float d = pmax - g_ptrg[j];
        s1 += (d > 0.f) ? 1.f : ((d < 0.f) ? -1.f : 0.f);
    }
    ss[tid] = s1;
    __syncthreads();
    for (int s = 512; s > 0; s >>= 1) {
        if (tid < s) ss[tid] += ss[tid + s];
        __syncthreads();
    }
    if (tid == 0) {
        g_istar      = istar;
        g_cstar      = g_rowarg[istar];
        g_rmaxstar   = g_rowmax[istar];
        g_sumexpstar = g_sumexp[istar];
        // loss has the scalar term summed over all B rows of the (B,B) broadcast
        g_coef = BETAc * 2048.0f * ss[0] * pmax;
    }
}

// fused gradient + Adam update
__global__ void step_kernel(float* __restrict__ u, float bc1, float bc2) {
    int idx = blockIdx.x * 256 + threadIdx.x;   // exactly 2048*1000 threads
    int i = idx / NCLS;
    int c = idx - i * NCLS;
    float uv = u[idx];

    float g = 0.f;
    int s = g_start[c];
    int e = s + g_count[c];
    int base = i << 11;
    for (int k = s; k < e; ++k) {
        float d = uv - g_topu[g_member[k]] - g_T[base + k];
        g += (d > 0.f) ? 1.f : ((d < 0.f) ? -1.f : 0.f);
    }
    if (i == g_istar) {
        float p = expf(uv - g_rmaxstar) / g_sumexpstar;
        float ind = (c == g_cstar) ? 1.f : 0.f;
        g += g_coef * (ind - p);
    }

    float mv = B1c * g_m[idx] + (1.0f - B1c) * g;
    float vv = B2c * g_v[idx] + (1.0f - B2c) * g * g;
    g_m[idx] = mv;
    g_v[idx] = vv;
    float mhat = mv / bc1;
    float vhat = vv / bc2;
    u[idx] = uv - LRc * mhat / (sqrtf(vhat) + EPSc);
}

// ---------------- launch ----------------
extern "C" void kernel_launch(void* const* d_in, const int* in_sizes, int n_in,
                              void* d_out, int out_size) {
    // identify inputs by element count (robust to ordering)
    const float* x = nullptr; const float* W = nullptr; const float* b = nullptr;
    for (int i = 0; i < n_in; ++i) {
        if (in_sizes[i] == BROWS * KDIM)      x = (const float*)d_in[i];
        else if (in_sizes[i] == KDIM * NCLS)  W = (const float*)d_in[i];
        else if (in_sizes[i] == NCLS)         b = (const float*)d_in[i];
    }
    float* u = (float*)d_out;

    dim3 gemm_grid((NCLS + 63) / 64, BROWS / 64);
    gemm_kernel<<<gemm_grid, 256>>>(x, W, b);

    init_class_kernel<<<4, 256>>>();
    stats_kernel<<<BROWS, 256>>>(nullptr, 0, 1);     // on z: y, p_trg, (rowstats)
    mark_kernel<<<8, 256>>>();
    scan_kernel<<<1, 1>>>();
    scatter_kernel<<<8, 256>>>();
    topz_kernel<<<BROWS, 256>>>();
    computeT_kernel<<<(BROWS * BROWS) / 256, 256>>>();
    init_u_kernel<<<(BROWS * NCLS) / 256, 256>>>(u);

    for (int t = 1; t <= NSTEPS; ++t) {
        stats_kernel<<<BROWS, 256>>>(u, 1, 0);
        reduce_kernel<<<1, 1024>>>();
        float bc1 = (float)(1.0 - pow((double)B1c, (double)t));
        float bc2 = (float)(1.0 - pow((double)B2c, (double)t));
        step_kernel<<<(BROWS * NCLS) / 256, 256>>>(u, bc1, bc2);
    }
}